// round 2
// baseline (speedup 1.0000x reference)
#include <cuda_runtime.h>
#include <cstdint>

// Problem constants (fixed by the dataset)
#define U_ROWS 50000
#define N_ITEMS 4000
#define BATCH 256
#define MAXK 64

// GEMM tiling
#define BM 128
#define BN 128
#define BK 16
#define KITERS (N_ITEMS / BK)   // 250

// ---------------- scratch (static device memory; no cudaMalloc allowed) ----
__device__ float g_sim[(size_t)BATCH * U_ROWS];      // 51.2 MB  sim[b*U + u]
__device__ float g_users[(size_t)BATCH * N_ITEMS];   // 4 MB gathered user rows
__device__ float g_inv_na[50048];                    // 1/max(||F_u||^2, eps), padded
__device__ float g_inv_nu[BATCH];                    // 1/max(||user_b||^2, eps)
__device__ float g_nb_val[BATCH * MAXK];
__device__ int   g_nb_idx[BATCH * MAXK];
__device__ int   g_k;
__device__ int   g_is64;

// ---------------- small helpers -------------------------------------------
__device__ __forceinline__ unsigned long long dup_f32x2(float a) {
    unsigned long long r;
    asm("mov.b64 %0, {%1, %1};" : "=l"(r) : "f"(a));
    return r;
}
__device__ __forceinline__ void fma_f32x2(unsigned long long& d,
                                          unsigned long long a,
                                          unsigned long long b) {
    asm("fma.rn.f32x2 %0, %1, %2, %0;" : "+l"(d) : "l"(a), "l"(b));
}
__device__ __forceinline__ float2 unpack_f32x2(unsigned long long v) {
    float2 r;
    asm("mov.b64 {%0, %1}, %2;" : "=f"(r.x), "=f"(r.y) : "l"(v));
    return r;
}
__device__ __forceinline__ float neg_inf() { return __int_as_float(0xFF800000); }

// ---------------- kernel 0: dtype/mode + k detection -----------------------
__global__ void mode_kernel(const void* ids, const int* kptr, int has_k) {
    if (threadIdx.x == 0) {
        const unsigned* w = (const unsigned*)ids;
        bool is64 = true;
        // int64 little-endian small positive values => every odd 32-bit word is 0
        for (int i = 0; i < 16; i++) {
            if (w[2 * i + 1] != 0u) { is64 = false; break; }
        }
        g_is64 = is64 ? 1 : 0;

        int kk = 10;
        if (has_k) {
            int vi = kptr[0];                      // int32, or low word of int64
            if (vi >= 1 && vi <= MAXK) {
                kk = vi;
            } else {
                float vf = __int_as_float(vi);     // maybe it arrived as float32
                if (vf >= 1.f && vf <= (float)MAXK) kk = (int)vf;
            }
        }
        g_k = kk;
    }
}

// ---------------- kernel 1: row norms (sum of squares) ---------------------
__global__ void norms_kernel(const float* __restrict__ F) {
    int u = blockIdx.x;
    int tid = threadIdx.x;
    const float4* row = (const float4*)(F + (size_t)u * N_ITEMS);
    float s = 0.f;
    for (int v = tid; v < N_ITEMS / 4; v += 256) {
        float4 x = row[v];
        s += x.x * x.x + x.y * x.y + x.z * x.z + x.w * x.w;
    }
    // warp reduce
    for (int off = 16; off > 0; off >>= 1)
        s += __shfl_down_sync(0xFFFFFFFFu, s, off);
    __shared__ float ws[8];
    if ((tid & 31) == 0) ws[tid >> 5] = s;
    __syncthreads();
    if (tid == 0) {
        float t = 0.f;
        for (int i = 0; i < 8; i++) t += ws[i];
        g_inv_na[u] = 1.0f / fmaxf(t, 1e-8f);
    }
}

// ---------------- kernel 2: gather user rows --------------------------------
__global__ void gather_users_kernel(const float* __restrict__ F, const void* ids) {
    int b = blockIdx.x;
    int tid = threadIdx.x;
    long long uid;
    if (g_is64) uid = ((const long long*)ids)[b];
    else        uid = (long long)((const int*)ids)[b];
    const float4* src = (const float4*)(F + (size_t)uid * N_ITEMS);
    float4* dst = (float4*)(g_users + (size_t)b * N_ITEMS);
    for (int v = tid; v < N_ITEMS / 4; v += 256) dst[v] = src[v];
    if (tid == 0) g_inv_nu[b] = g_inv_na[uid];
}

// ---------------- kernel 3: GEMM + scaling -> g_sim[b][u] -------------------
// C[u,b] = dot(F[u,:], users[b,:]);  sim[b,u] = C * inv_na[u] * inv_nu[b]
__global__ __launch_bounds__(256, 1)
void gemm_sim_kernel(const float* __restrict__ F) {
    __shared__ float As[BK][BM];   // As[k][m]
    __shared__ float Bs[BK][BN];   // Bs[k][n]

    const int m0 = blockIdx.x * BM;
    const int n0 = blockIdx.y * BN;
    const int tid = threadIdx.x;
    const int tx = tid & 15;
    const int ty = tid >> 4;

    // loader role: threads 0..127 load A rows, 128..255 load B rows
    const bool loadA = tid < 128;
    const int lrow = loadA ? tid : tid - 128;
    const float* gptr;
    if (loadA) {
        int gm = min(m0 + lrow, U_ROWS - 1);
        gptr = F + (size_t)gm * N_ITEMS;
    } else {
        gptr = g_users + (size_t)(n0 + lrow) * N_ITEMS;
    }

    float4 t0 = ((const float4*)gptr)[0];
    float4 t1 = ((const float4*)gptr)[1];
    float4 t2 = ((const float4*)gptr)[2];
    float4 t3 = ((const float4*)gptr)[3];

    unsigned long long acc[8][4];
#pragma unroll
    for (int i = 0; i < 8; i++)
#pragma unroll
        for (int j = 0; j < 4; j++) acc[i][j] = 0ull;

    for (int kt = 0; kt < KITERS; ++kt) {
        // store staged regs to smem (transposed)
        if (loadA) {
            As[0][lrow] = t0.x;  As[1][lrow] = t0.y;  As[2][lrow] = t0.z;  As[3][lrow] = t0.w;
            As[4][lrow] = t1.x;  As[5][lrow] = t1.y;  As[6][lrow] = t1.z;  As[7][lrow] = t1.w;
            As[8][lrow] = t2.x;  As[9][lrow] = t2.y;  As[10][lrow] = t2.z; As[11][lrow] = t2.w;
            As[12][lrow] = t3.x; As[13][lrow] = t3.y; As[14][lrow] = t3.z; As[15][lrow] = t3.w;
        } else {
            Bs[0][lrow] = t0.x;  Bs[1][lrow] = t0.y;  Bs[2][lrow] = t0.z;  Bs[3][lrow] = t0.w;
            Bs[4][lrow] = t1.x;  Bs[5][lrow] = t1.y;  Bs[6][lrow] = t1.z;  Bs[7][lrow] = t1.w;
            Bs[8][lrow] = t2.x;  Bs[9][lrow] = t2.y;  Bs[10][lrow] = t2.z; Bs[11][lrow] = t2.w;
            Bs[12][lrow] = t3.x; Bs[13][lrow] = t3.y; Bs[14][lrow] = t3.z; Bs[15][lrow] = t3.w;
        }
        __syncthreads();

        // prefetch next K tile (global -> regs) while we compute
        if (kt + 1 < KITERS) {
            gptr += BK;
            t0 = ((const float4*)gptr)[0];
            t1 = ((const float4*)gptr)[1];
            t2 = ((const float4*)gptr)[2];
            t3 = ((const float4*)gptr)[3];
        }

#pragma unroll
        for (int k = 0; k < BK; ++k) {
            float4 a0 = *(const float4*)&As[k][ty * 4];
            float4 a1 = *(const float4*)&As[k][64 + ty * 4];
            ulonglong2 b0 = *(const ulonglong2*)&Bs[k][tx * 4];
            ulonglong2 b1 = *(const ulonglong2*)&Bs[k][64 + tx * 4];

            unsigned long long ad[8];
            ad[0] = dup_f32x2(a0.x); ad[1] = dup_f32x2(a0.y);
            ad[2] = dup_f32x2(a0.z); ad[3] = dup_f32x2(a0.w);
            ad[4] = dup_f32x2(a1.x); ad[5] = dup_f32x2(a1.y);
            ad[6] = dup_f32x2(a1.z); ad[7] = dup_f32x2(a1.w);

#pragma unroll
            for (int i = 0; i < 8; i++) {
                fma_f32x2(acc[i][0], ad[i], b0.x);
                fma_f32x2(acc[i][1], ad[i], b0.y);
                fma_f32x2(acc[i][2], ad[i], b1.x);
                fma_f32x2(acc[i][3], ad[i], b1.y);
            }
        }
        __syncthreads();
    }

    // unpack accumulators: c[i][j], rows i: {ty*4+ii, 64+ty*4+ii}, cols j: {tx*4+jj, 64+tx*4+jj}
    float c[8][8];
#pragma unroll
    for (int i = 0; i < 8; i++)
#pragma unroll
        for (int p = 0; p < 4; p++) {
            float2 v = unpack_f32x2(acc[i][p]);
            c[i][2 * p + 0] = v.x;
            c[i][2 * p + 1] = v.y;
        }

    float4 ina0 = *(const float4*)&g_inv_na[m0 + ty * 4];
    float4 ina1 = *(const float4*)&g_inv_na[m0 + 64 + ty * 4];
    float4 inu0 = *(const float4*)&g_inv_nu[n0 + tx * 4];
    float4 inu1 = *(const float4*)&g_inv_nu[n0 + 64 + tx * 4];
    float inu[8] = {inu0.x, inu0.y, inu0.z, inu0.w, inu1.x, inu1.y, inu1.z, inu1.w};
    float ina[8] = {ina0.x, ina0.y, ina0.z, ina0.w, ina1.x, ina1.y, ina1.z, ina1.w};

#pragma unroll
    for (int j = 0; j < 8; j++) {
        int b = n0 + ((j < 4) ? (tx * 4 + j) : (64 + tx * 4 + (j - 4)));
        float s = inu[j];
        float* simb = g_sim + (size_t)b * U_ROWS;

        int u0 = m0 + ty * 4;              // always < U_ROWS (m0<=49920, ty*4<=60)
        float4 o0;
        o0.x = c[0][j] * ina[0] * s;
        o0.y = c[1][j] * ina[1] * s;
        o0.z = c[2][j] * ina[2] * s;
        o0.w = c[3][j] * ina[3] * s;
        *(float4*)&simb[u0] = o0;

        int u1 = m0 + 64 + ty * 4;
        if (u1 < U_ROWS) {
            float4 o1;
            o1.x = c[4][j] * ina[4] * s;
            o1.y = c[5][j] * ina[5] * s;
            o1.z = c[6][j] * ina[6] * s;
            o1.w = c[7][j] * ina[7] * s;
            *(float4*)&simb[u1] = o1;
        }
    }
}

// ---------------- kernel 4: top-k per batch row -----------------------------
__global__ void topk_kernel() {
    const int b = blockIdx.x;
    const int tid = threadIdx.x;
    const int k = g_k;

    float lv[MAXK];
    int   li[MAXK];
    for (int j = 0; j < k; j++) { lv[j] = neg_inf(); li[j] = 0x7FFFFFFF; }

    const float* row = g_sim + (size_t)b * U_ROWS;
    for (int u = tid; u < U_ROWS; u += 256) {
        float v = row[u];
        if (v > lv[k - 1]) {
            int p = k - 1;
            while (p > 0 && lv[p - 1] < v) {
                lv[p] = lv[p - 1];
                li[p] = li[p - 1];
                --p;
            }
            lv[p] = v;
            li[p] = u;
        }
    }

    __shared__ unsigned long long rk[256];
    __shared__ int rt[256];
    int head = 0;

    for (int r = 0; r < k; r++) {
        float v = (head < k) ? lv[head] : neg_inf();
        int  id = (head < k) ? li[head] : 0x7FFFFFFF;
        unsigned kb = __float_as_uint(v);
        kb = kb ^ ((kb >> 31) ? 0xFFFFFFFFu : 0x80000000u);  // order-preserving map
        // tie-break: lower index wins (matches jax top_k)
        rk[tid] = ((unsigned long long)kb << 32) |
                  (unsigned long long)(0xFFFFFFFFu - (unsigned)id);
        rt[tid] = tid;
        __syncthreads();
        for (int s = 128; s > 0; s >>= 1) {
            if (tid < s && rk[tid + s] > rk[tid]) {
                rk[tid] = rk[tid + s];
                rt[tid] = rt[tid + s];
            }
            __syncthreads();
        }
        int w = rt[0];
        if (tid == w) {
            g_nb_val[b * MAXK + r] = lv[head];
            g_nb_idx[b * MAXK + r] = li[head];
            head++;
        }
        __syncthreads();
    }
}

// ---------------- kernel 5: weighted neighbor gather ------------------------
__global__ void ratings_kernel(const float* __restrict__ F, float* __restrict__ out) {
    const int b = blockIdx.x;
    const int tid = threadIdx.x;
    const int k = g_k;

    __shared__ float w[MAXK];
    __shared__ int   id[MAXK];
    if (tid == 0) {
        float s = 0.f;
        for (int j = 0; j < k; j++) s += g_nb_val[b * MAXK + j];
        float inv = 1.0f / s;
        for (int j = 0; j < k; j++) {
            w[j]  = g_nb_val[b * MAXK + j] * inv;
            id[j] = g_nb_idx[b * MAXK + j];
        }
    }
    __syncthreads();

    for (int i = tid; i < N_ITEMS; i += 256) {
        float acc = 0.f;
        for (int j = 0; j < k; j++)
            acc += w[j] * F[(size_t)id[j] * N_ITEMS + i];
        out[(size_t)b * N_ITEMS + i] = acc;
    }
}

// ---------------- launch ----------------------------------------------------
extern "C" void kernel_launch(void* const* d_in, const int* in_sizes, int n_in,
                              void* d_out, int out_size) {
    const float* F = (const float*)d_in[0];
    const void* ids = d_in[1];
    const int* kptr = (n_in > 2) ? (const int*)d_in[2] : nullptr;

    mode_kernel<<<1, 32>>>(ids, kptr, kptr != nullptr ? 1 : 0);
    norms_kernel<<<U_ROWS, 256>>>(F);
    gather_users_kernel<<<BATCH, 256>>>(F, ids);

    dim3 grid((U_ROWS + BM - 1) / BM, BATCH / BN);
    gemm_sim_kernel<<<grid, 256>>>(F);

    topk_kernel<<<BATCH, 256>>>();
    ratings_kernel<<<BATCH, 256>>>(F, (float*)d_out);
}

// round 5
// speedup vs baseline: 4.3678x; 4.3678x over previous
#include <cuda_runtime.h>
#include <cuda_bf16.h>
#include <cstdint>

// Problem constants
#define U_ROWS 50000
#define N_ITEMS 4000
#define BATCH 256
#define MAXK 64
#define CAND 32                 // approx candidates per row, rescored exactly

// GEMM config: CTA tile 128(M) x 256(N), BK=32 bf16 (64B rows), 4-stage cp.async
#define BK 32
#define KITERS (N_ITEMS / BK)   // 125
#define NSTAGE 4
#define NTHREADS 512            // 16 warps: 2(M) x 8(N), warp tile 64x32

#define STAGE_BYTES 24576       // A 128x64B (8K) + B 256x64B (16K)
#define OFF_INVNA 131584        // after Csm region (128*257*4 = 131584)
#define OFF_INVNU (OFF_INVNA + 512)
#define SMEM_TOTAL (OFF_INVNU + 1024 + 128)

// ---------------- scratch (static device memory) ---------------------------
__device__ __align__(16) __nv_bfloat16 g_Fb[(size_t)U_ROWS * N_ITEMS];     // 400 MB
__device__ __align__(16) float g_sim[(size_t)BATCH * U_ROWS];              // 51.2 MB [b][u]
__device__ __align__(16) float g_users[(size_t)BATCH * N_ITEMS];           // 4 MB fp32
__device__ __align__(16) __nv_bfloat16 g_users_bf[(size_t)BATCH * N_ITEMS];// 2 MB
__device__ float g_inv_na[50176];   // exact 1/max(||F_u||^2,eps), padded (pad reads ok)
__device__ float g_inv_nu[BATCH];
__device__ int   g_cand_idx[BATCH * CAND];
__device__ float g_nb_val[BATCH * MAXK];
__device__ int   g_nb_idx[BATCH * MAXK];
__device__ int   g_k;
__device__ int   g_is64;

// ---------------- helpers ---------------------------------------------------
__device__ __forceinline__ uint32_t smem_u32(const void* p) {
    uint32_t a;
    asm("{ .reg .u64 t; cvta.to.shared.u64 t, %1; cvt.u32.u64 %0, t; }" : "=r"(a) : "l"(p));
    return a;
}
#define CP_ASYNC16(dst, src) \
    asm volatile("cp.async.cg.shared.global [%0], [%1], 16;" :: "r"(dst), "l"(src))
#define CP_COMMIT() asm volatile("cp.async.commit_group;" ::: "memory")
#define CP_WAIT(n)  asm volatile("cp.async.wait_group %0;" :: "n"(n) : "memory")

__device__ __forceinline__ float neg_inf() { return __int_as_float(0xFF800000); }
__device__ __forceinline__ unsigned bf16u(float x) {
    return (unsigned)__bfloat16_as_ushort(__float2bfloat16_rn(x));
}
// swizzled chunk byte offset within a 64B-row tile
__device__ __forceinline__ uint32_t swz64(int row, int c) {
    return (uint32_t)(row * 64 + 16 * (c ^ ((row >> 1) & 3)));
}

// ---------------- kernel 0: dtype/mode + k detection ------------------------
__global__ void mode_kernel(const void* ids, const int* kptr, int has_k) {
    if (threadIdx.x == 0) {
        const unsigned* w = (const unsigned*)ids;
        bool is64 = true;
        for (int i = 0; i < 16; i++)
            if (w[2 * i + 1] != 0u) { is64 = false; break; }
        g_is64 = is64 ? 1 : 0;

        int kk = 10;
        if (has_k) {
            int vi = kptr[0];
            if (vi >= 1 && vi <= MAXK) kk = vi;
            else {
                float vf = __int_as_float(vi);
                if (vf >= 1.f && vf <= (float)MAXK) kk = (int)vf;
            }
        }
        g_k = kk;
    }
}

// ---------------- kernel 1: convert F -> bf16 + exact row norms -------------
__global__ void convert_kernel(const float* __restrict__ F) {
    const int u = blockIdx.x;
    const int tid = threadIdx.x;
    const float4* src = (const float4*)(F + (size_t)u * N_ITEMS);
    uint2* dst = (uint2*)(g_Fb + (size_t)u * N_ITEMS);
    float s = 0.f;
    for (int v = tid; v < N_ITEMS / 4; v += 256) {
        float4 x = src[v];
        s += x.x * x.x + x.y * x.y + x.z * x.z + x.w * x.w;
        uint2 o;
        o.x = bf16u(x.x) | (bf16u(x.y) << 16);
        o.y = bf16u(x.z) | (bf16u(x.w) << 16);
        dst[v] = o;
    }
    for (int off = 16; off > 0; off >>= 1)
        s += __shfl_down_sync(0xFFFFFFFFu, s, off);
    __shared__ float ws[8];
    if ((tid & 31) == 0) ws[tid >> 5] = s;
    __syncthreads();
    if (tid == 0) {
        float t = 0.f;
        for (int i = 0; i < 8; i++) t += ws[i];
        g_inv_na[u] = 1.0f / fmaxf(t, 1e-8f);
    }
}

// ---------------- kernel 2: gather user rows (fp32 + bf16) + exact norms ----
__global__ void gather_users_kernel(const float* __restrict__ F, const void* ids) {
    const int b = blockIdx.x;
    const int tid = threadIdx.x;
    long long uid;
    if (g_is64) uid = ((const long long*)ids)[b];
    else        uid = (long long)((const int*)ids)[b];
    const float4* src = (const float4*)(F + (size_t)uid * N_ITEMS);
    float4* dstf = (float4*)(g_users + (size_t)b * N_ITEMS);
    uint2* dstb = (uint2*)(g_users_bf + (size_t)b * N_ITEMS);
    float s = 0.f;
    for (int v = tid; v < N_ITEMS / 4; v += 256) {
        float4 x = src[v];
        dstf[v] = x;
        uint2 o;
        o.x = bf16u(x.x) | (bf16u(x.y) << 16);
        o.y = bf16u(x.z) | (bf16u(x.w) << 16);
        dstb[v] = o;
        s += x.x * x.x + x.y * x.y + x.z * x.z + x.w * x.w;
    }
    for (int off = 16; off > 0; off >>= 1)
        s += __shfl_down_sync(0xFFFFFFFFu, s, off);
    __shared__ float ws[8];
    if ((tid & 31) == 0) ws[tid >> 5] = s;
    __syncthreads();
    if (tid == 0) {
        float t = 0.f;
        for (int i = 0; i < 8; i++) t += ws[i];
        g_inv_nu[b] = 1.0f / fmaxf(t, 1e-8f);
    }
}

// ---------------- kernel 3: bf16 mma.sync GEMM -> scaled approx sims --------
__global__ __launch_bounds__(NTHREADS, 1)
void gemm_sim_kernel() {
    extern __shared__ __align__(1024) char smem[];
    const uint32_t sbase = smem_u32(smem);
    const int tid = threadIdx.x;
    const int lane = tid & 31;
    const int wid = tid >> 5;
    const int m0 = blockIdx.x * 128;
    const int mw = wid & 1;       // warp M index
    const int nw = wid >> 1;      // warp N index

    // stage exact inverse norms into smem (region beyond stages/Csm)
    float* invna_s = (float*)(smem + OFF_INVNA);
    float* invnu_s = (float*)(smem + OFF_INVNU);
    if (tid < 128) invna_s[tid] = g_inv_na[m0 + tid < 50176 ? m0 + tid : 50175];
    if (tid < 256) invnu_s[tid] = g_inv_nu[tid];

    float c[4][4][4];
#pragma unroll
    for (int f = 0; f < 4; f++)
#pragma unroll
        for (int g = 0; g < 4; g++)
#pragma unroll
            for (int i = 0; i < 4; i++) c[f][g][i] = 0.f;

    // ---- tile loader: A 512 chunks (1/thread), B 1024 chunks (2/thread) ----
    auto issue = [&](int stage, int kt) {
        uint32_t ab = sbase + stage * STAGE_BYTES;
        uint32_t bb = ab + 8192;
        {
            int row = tid >> 2, ch = tid & 3;
            int gm = m0 + row; gm = gm < U_ROWS ? gm : U_ROWS - 1;
            const char* src = (const char*)g_Fb + (size_t)gm * (N_ITEMS * 2) +
                              kt * (BK * 2) + ch * 16;
            CP_ASYNC16(ab + swz64(row, ch), src);
        }
#pragma unroll
        for (int i = 0; i < 2; i++) {
            int e = tid + 512 * i;
            int row = e >> 2, ch = e & 3;
            const char* src = (const char*)g_users_bf + (size_t)row * (N_ITEMS * 2) +
                              kt * (BK * 2) + ch * 16;
            CP_ASYNC16(bb + swz64(row, ch), src);
        }
    };

    issue(0, 0); CP_COMMIT();
    issue(1, 1); CP_COMMIT();
    issue(2, 2); CP_COMMIT();

    for (int kt = 0; kt < KITERS; ++kt) {
        const int st = kt & 3;   // NSTAGE == 4
        CP_WAIT(2);
        __syncthreads();
        if (kt + 3 < KITERS) issue((kt + 3) & 3, kt + 3);
        CP_COMMIT();

        const uint32_t ab = sbase + st * STAGE_BYTES;
        const char* bbp = smem + st * STAGE_BYTES + 8192;

#pragma unroll
        for (int s = 0; s < 2; ++s) {         // two k16 steps in BK=32
            uint32_t af[4][4];
#pragma unroll
            for (int f = 0; f < 4; ++f) {
                int row = mw * 64 + f * 16 + (lane & 15);
                int ch = 2 * s + (lane >> 4);
                uint32_t addr = ab + swz64(row, ch);
                asm volatile("ldmatrix.sync.aligned.m8n8.x4.shared.b16 {%0,%1,%2,%3}, [%4];"
                             : "=r"(af[f][0]), "=r"(af[f][1]), "=r"(af[f][2]), "=r"(af[f][3])
                             : "r"(addr));
            }
            uint32_t bfr[4][2];
#pragma unroll
            for (int g = 0; g < 4; ++g) {
                int n = nw * 32 + g * 8 + (lane >> 2);
                const char* nb = bbp + n * 64 + 4 * (lane & 3);
                bfr[g][0] = *(const uint32_t*)(nb + 16 * ((2 * s)     ^ ((n >> 1) & 3)));
                bfr[g][1] = *(const uint32_t*)(nb + 16 * ((2 * s + 1) ^ ((n >> 1) & 3)));
            }
#pragma unroll
            for (int f = 0; f < 4; ++f)
#pragma unroll
                for (int g = 0; g < 4; ++g) {
                    asm volatile(
                        "mma.sync.aligned.m16n8k16.row.col.f32.bf16.bf16.f32 "
                        "{%0,%1,%2,%3}, {%4,%5,%6,%7}, {%8,%9}, {%0,%1,%2,%3};"
                        : "+f"(c[f][g][0]), "+f"(c[f][g][1]),
                          "+f"(c[f][g][2]), "+f"(c[f][g][3])
                        : "r"(af[f][0]), "r"(af[f][1]), "r"(af[f][2]), "r"(af[f][3]),
                          "r"(bfr[g][0]), "r"(bfr[g][1]));
                }
        }
    }

    CP_WAIT(0);
    __syncthreads();

    // ---- scale + stage to smem [128][257] (stages region reused) ----
    float* Csm = (float*)smem;
#pragma unroll
    for (int f = 0; f < 4; ++f) {
        int r0 = mw * 64 + f * 16 + (lane >> 2);
        float na0 = invna_s[r0], na8 = invna_s[r0 + 8];
#pragma unroll
        for (int g = 0; g < 4; ++g) {
            int col = nw * 32 + g * 8 + 2 * (lane & 3);
            float nu0 = invnu_s[col], nu1 = invnu_s[col + 1];
            Csm[r0 * 257 + col]           = c[f][g][0] * na0 * nu0;
            Csm[r0 * 257 + col + 1]       = c[f][g][1] * na0 * nu1;
            Csm[(r0 + 8) * 257 + col]     = c[f][g][2] * na8 * nu0;
            Csm[(r0 + 8) * 257 + col + 1] = c[f][g][3] * na8 * nu1;
        }
    }
    __syncthreads();

    // ---- coalesced write-out: warp w -> users b = w*16 .. w*16+15 ----
    for (int it = 0; it < 16; ++it) {
        int b = wid * 16 + it;
        float* dst = g_sim + (size_t)b * U_ROWS + m0;
#pragma unroll
        for (int j = 0; j < 4; ++j) {
            int r = lane + 32 * j;
            if (m0 + r < U_ROWS) dst[r] = Csm[r * 257 + b];
        }
    }
}

// ---------------- kernel 4: approx top-CAND candidate selection -------------
#define LOCK 8
__global__ void topk_cand_kernel() {
    const int b = blockIdx.x;
    const int tid = threadIdx.x;
    const int lane = tid & 31;
    const int wid = tid >> 5;

    float lv[LOCK];
    int   li[LOCK];
#pragma unroll
    for (int j = 0; j < LOCK; j++) { lv[j] = neg_inf(); li[j] = 0x7FFFFFFF; }

    const float* row = g_sim + (size_t)b * U_ROWS;
    for (int u = tid; u < U_ROWS; u += 256) {
        float v = row[u];
        if (v > lv[LOCK - 1]) {
            float cv = v; int ci = u;
#pragma unroll
            for (int j = 0; j < LOCK; j++) {
                if (cv > lv[j]) {
                    float tv = lv[j]; int ti = li[j];
                    lv[j] = cv; li[j] = ci;
                    cv = tv; ci = ti;
                }
            }
        }
    }

    __shared__ unsigned long long wbest[8];
    __shared__ int wtid[8];
    __shared__ int swin;

    for (int r = 0; r < CAND; ++r) {
        unsigned kb = __float_as_uint(lv[0]);
        kb ^= (kb >> 31) ? 0xFFFFFFFFu : 0x80000000u;
        unsigned long long best = ((unsigned long long)kb << 32) |
                                  (unsigned long long)(0xFFFFFFFFu - (unsigned)li[0]);
        int bt = tid;
#pragma unroll
        for (int o = 16; o > 0; o >>= 1) {
            unsigned long long ob = __shfl_down_sync(0xFFFFFFFFu, best, o);
            int ot = __shfl_down_sync(0xFFFFFFFFu, bt, o);
            if (ob > best) { best = ob; bt = ot; }
        }
        if (lane == 0) { wbest[wid] = best; wtid[wid] = bt; }
        __syncthreads();
        if (tid == 0) {
            unsigned long long m = wbest[0]; int mt = wtid[0];
            for (int i = 1; i < 8; i++)
                if (wbest[i] > m) { m = wbest[i]; mt = wtid[i]; }
            swin = mt;
        }
        __syncthreads();
        if (tid == swin) {
            g_cand_idx[b * CAND + r] = li[0];
#pragma unroll
            for (int j = 0; j < LOCK - 1; j++) { lv[j] = lv[j + 1]; li[j] = li[j + 1]; }
            lv[LOCK - 1] = neg_inf(); li[LOCK - 1] = 0x7FFFFFFF;
        }
        __syncthreads();
    }
}

// ---------------- kernel 5: exact fp32 rescore + top-k ----------------------
__global__ void rescore_kernel(const float* __restrict__ F) {
    const int b = blockIdx.x;
    const int tid = threadIdx.x;
    const int lane = tid & 31;
    const int w = tid >> 5;

    __shared__ float ssim[CAND];
    __shared__ int   sidx[CAND];

    const float* ub = g_users + (size_t)b * N_ITEMS;
    for (int cc = w; cc < CAND; cc += 8) {
        int u = g_cand_idx[b * CAND + cc];
        const float* fu = F + (size_t)u * N_ITEMS;
        float acc = 0.f;
        for (int k = lane; k < N_ITEMS; k += 32)
            acc += ub[k] * fu[k];
        for (int o = 16; o > 0; o >>= 1)
            acc += __shfl_down_sync(0xFFFFFFFFu, acc, o);
        if (lane == 0) {
            ssim[cc] = acc * g_inv_na[u] * g_inv_nu[b];
            sidx[cc] = u;
        }
    }
    __syncthreads();

    if (tid == 0) {
        int k = g_k < CAND ? g_k : CAND;
        bool used[CAND];
        for (int i = 0; i < CAND; i++) used[i] = false;
        for (int r = 0; r < k; r++) {
            int bi = -1;
            float bv = neg_inf();
            int bidx = 0x7FFFFFFF;
            for (int cc = 0; cc < CAND; cc++) {
                if (used[cc]) continue;
                float v = ssim[cc];
                if (v > bv || (v == bv && sidx[cc] < bidx)) {
                    bv = v; bidx = sidx[cc]; bi = cc;
                }
            }
            used[bi] = true;
            g_nb_val[b * MAXK + r] = bv;
            g_nb_idx[b * MAXK + r] = bidx;
        }
    }
}

// ---------------- kernel 6: weighted neighbor gather ------------------------
__global__ void ratings_kernel(const float* __restrict__ F, float* __restrict__ out) {
    const int b = blockIdx.x;
    const int tid = threadIdx.x;
    const int k = g_k < CAND ? g_k : CAND;

    __shared__ float w[MAXK];
    __shared__ int   id[MAXK];
    if (tid == 0) {
        float s = 0.f;
        for (int j = 0; j < k; j++) s += g_nb_val[b * MAXK + j];
        float inv = 1.0f / s;
        for (int j = 0; j < k; j++) {
            w[j]  = g_nb_val[b * MAXK + j] * inv;
            id[j] = g_nb_idx[b * MAXK + j];
        }
    }
    __syncthreads();

    for (int i = tid; i < N_ITEMS; i += 256) {
        float acc = 0.f;
        for (int j = 0; j < k; j++)
            acc += w[j] * F[(size_t)id[j] * N_ITEMS + i];
        out[(size_t)b * N_ITEMS + i] = acc;
    }
}

// ---------------- launch ----------------------------------------------------
extern "C" void kernel_launch(void* const* d_in, const int* in_sizes, int n_in,
                              void* d_out, int out_size) {
    const float* F = (const float*)d_in[0];
    const void* ids = d_in[1];
    const int* kptr = (n_in > 2) ? (const int*)d_in[2] : nullptr;

    cudaFuncSetAttribute(gemm_sim_kernel,
                         cudaFuncAttributeMaxDynamicSharedMemorySize, SMEM_TOTAL);

    mode_kernel<<<1, 32>>>(ids, kptr, kptr != nullptr ? 1 : 0);
    convert_kernel<<<U_ROWS, 256>>>(F);
    gather_users_kernel<<<BATCH, 256>>>(F, ids);

    int grid = (U_ROWS + 127) / 128;   // 391
    gemm_sim_kernel<<<grid, NTHREADS, SMEM_TOTAL>>>();

    topk_cand_kernel<<<BATCH, 256>>>();
    rescore_kernel<<<BATCH, 256>>>(F);
    ratings_kernel<<<BATCH, 256>>>(F, (float*)d_out);
}

// round 6
// speedup vs baseline: 6.2343x; 1.4273x over previous
#include <cuda_runtime.h>
#include <cuda_bf16.h>
#include <cstdint>

// Problem constants
#define U_ROWS 50000
#define N_ITEMS 4000
#define BATCH 256
#define MAXK 64
#define CAND 32                 // approx candidates per row, rescored exactly

// GEMM config: CTA tile 128(M) x 256(N), BK=32, 3-stage smem ring
// A: fp32 LDG -> cvt -> bf16 STS (fused convert). B: bf16 cp.async.
#define BK 32
#define KITERS (N_ITEMS / BK)   // 125
#define NTHREADS 512            // 16 warps: 2(M) x 8(N), warp tile 64x32

#define STAGE_BYTES 24576       // A bf16 128x64B (8K) + B bf16 256x64B (16K)
#define OFF_INVNA (3 * STAGE_BYTES)        // 73728
#define OFF_INVNU (OFF_INVNA + 512)
#define SMEM_TOTAL (OFF_INVNU + 1024 + 64)

// ---------------- scratch (static device memory) ---------------------------
__device__ __align__(16) float g_sim[(size_t)BATCH * U_ROWS];              // 51.2 MB [b][u]
__device__ __align__(16) float g_users[(size_t)BATCH * N_ITEMS];           // 4 MB fp32
__device__ __align__(16) __nv_bfloat16 g_users_bf[(size_t)BATCH * N_ITEMS];// 2 MB
__device__ float g_inv_na[U_ROWS];  // exact 1/max(||F_u||^2,eps), written by GEMM
__device__ float g_inv_nu[BATCH];
__device__ int   g_cand_idx[BATCH * CAND];
__device__ float g_nb_val[BATCH * MAXK];
__device__ int   g_nb_idx[BATCH * MAXK];
__device__ int   g_k;
__device__ int   g_is64;

// ---------------- helpers ---------------------------------------------------
__device__ __forceinline__ uint32_t smem_u32(const void* p) {
    uint32_t a;
    asm("{ .reg .u64 t; cvta.to.shared.u64 t, %1; cvt.u32.u64 %0, t; }" : "=r"(a) : "l"(p));
    return a;
}
#define CP_ASYNC16(dst, src) \
    asm volatile("cp.async.cg.shared.global [%0], [%1], 16;" :: "r"(dst), "l"(src))
#define CP_COMMIT() asm volatile("cp.async.commit_group;" ::: "memory")
#define CP_WAIT(n)  asm volatile("cp.async.wait_group %0;" :: "n"(n) : "memory")

__device__ __forceinline__ float neg_inf() { return __int_as_float(0xFF800000); }
__device__ __forceinline__ unsigned bf16u(float x) {
    return (unsigned)__bfloat16_as_ushort(__float2bfloat16_rn(x));
}
// pack two f32 -> bf16x2 (lo = a, hi = b)
__device__ __forceinline__ uint32_t pack_bf2(float a, float b) {
    uint32_t r;
    asm("cvt.rn.bf16x2.f32 %0, %2, %1;" : "=r"(r) : "f"(a), "f"(b));
    return r;
}
// swizzled chunk byte offset within a 64B-row tile
__device__ __forceinline__ uint32_t swz64(int row, int c) {
    return (uint32_t)(row * 64 + 16 * (c ^ ((row >> 1) & 3)));
}

// ---------------- kernel 0: dtype/mode + k detection ------------------------
__global__ void mode_kernel(const void* ids, const int* kptr, int has_k) {
    if (threadIdx.x == 0) {
        const unsigned* w = (const unsigned*)ids;
        bool is64 = true;
        for (int i = 0; i < 16; i++)
            if (w[2 * i + 1] != 0u) { is64 = false; break; }
        g_is64 = is64 ? 1 : 0;

        int kk = 10;
        if (has_k) {
            int vi = kptr[0];
            if (vi >= 1 && vi <= MAXK) kk = vi;
            else {
                float vf = __int_as_float(vi);
                if (vf >= 1.f && vf <= (float)MAXK) kk = (int)vf;
            }
        }
        g_k = kk;
    }
}

// ---------------- kernel 1: gather user rows (fp32 + bf16) + exact norms ----
__global__ void gather_users_kernel(const float* __restrict__ F, const void* ids) {
    const int b = blockIdx.x;
    const int tid = threadIdx.x;
    long long uid;
    if (g_is64) uid = ((const long long*)ids)[b];
    else        uid = (long long)((const int*)ids)[b];
    const float4* src = (const float4*)(F + (size_t)uid * N_ITEMS);
    float4* dstf = (float4*)(g_users + (size_t)b * N_ITEMS);
    uint2* dstb = (uint2*)(g_users_bf + (size_t)b * N_ITEMS);
    float s = 0.f;
    for (int v = tid; v < N_ITEMS / 4; v += 256) {
        float4 x = src[v];
        dstf[v] = x;
        uint2 o;
        o.x = bf16u(x.x) | (bf16u(x.y) << 16);
        o.y = bf16u(x.z) | (bf16u(x.w) << 16);
        dstb[v] = o;
        s += x.x * x.x + x.y * x.y + x.z * x.z + x.w * x.w;
    }
    for (int off = 16; off > 0; off >>= 1)
        s += __shfl_down_sync(0xFFFFFFFFu, s, off);
    __shared__ float ws[8];
    if ((tid & 31) == 0) ws[tid >> 5] = s;
    __syncthreads();
    if (tid == 0) {
        float t = 0.f;
        for (int i = 0; i < 8; i++) t += ws[i];
        g_inv_nu[b] = 1.0f / fmaxf(t, 1e-8f);
    }
}

// ---------------- kernel 2: bf16 mma GEMM, fused fp32->bf16 + exact norms ---
__global__ __launch_bounds__(NTHREADS, 1)
void gemm_sim_kernel(const float* __restrict__ F) {
    extern __shared__ __align__(1024) char smem[];
    const uint32_t sbase = smem_u32(smem);
    const int tid = threadIdx.x;
    const int lane = tid & 31;
    const int wid = tid >> 5;
    const int m0 = blockIdx.x * 128;
    const int mw = wid & 1;       // warp M index
    const int nw = wid >> 1;      // warp N index

    float* invna_s = (float*)(smem + OFF_INVNA);
    float* invnu_s = (float*)(smem + OFF_INVNU);
    if (tid < 256) invnu_s[tid] = g_inv_nu[tid];

    // ---- A producer (fp32 LDG -> cvt -> STS): thread owns (row, 16B chunk) ----
    const int arow = tid >> 2;           // 0..127
    const int ach = tid & 3;             // bf16 16B chunk == fp32 32B chunk
    int gm = m0 + arow; if (gm > U_ROWS - 1) gm = U_ROWS - 1;
    const char* asrc = (const char*)F + (size_t)gm * (N_ITEMS * 4) + ach * 32;
    const uint32_t asts = swz64(arow, ach);          // + stage base

    // ---- B producer (cp.async from bf16 users) ----
    const int brow = tid >> 2;           // rows brow, brow+128
    const char* bsrc0 = (const char*)g_users_bf + (size_t)brow * (N_ITEMS * 2) + ach * 16;
    const char* bsrc1 = bsrc0 + (size_t)128 * (N_ITEMS * 2);
    const uint32_t bst0 = 8192 + swz64(brow, ach);
    const uint32_t bst1 = 8192 + swz64(brow + 128, ach);

    // ---- A fragment (ldmatrix) per-lane constants ----
    const int ahalf = lane >> 4;
    uint32_t a_base[4];
    int a_sw[4];
#pragma unroll
    for (int f = 0; f < 4; f++) {
        int r = mw * 64 + f * 16 + (lane & 15);
        a_base[f] = (uint32_t)(r * 64);
        a_sw[f] = (r >> 1) & 3;
    }
    // ---- B fragment (ldmatrix x4 over 16n x 16k) per-lane constants ----
    const int grp = lane >> 3;
    const int cbit = grp & 1;
    uint32_t b_base[2];
    int b_sw[2];
#pragma unroll
    for (int gp = 0; gp < 2; gp++) {
        int n = nw * 32 + gp * 16 + ((grp & 2) << 2) + (lane & 7);
        b_base[gp] = (uint32_t)(8192 + n * 64);
        b_sw[gp] = (n >> 1) & 3;
    }

    float c[4][4][4];
#pragma unroll
    for (int f = 0; f < 4; f++)
#pragma unroll
        for (int g = 0; g < 4; g++)
#pragma unroll
            for (int i = 0; i < 4; i++) c[f][g][i] = 0.f;

    float ns = 0.f;          // partial sum-of-squares for row `arow`
    float4 av0, av1;         // A staging registers

    auto ldgA = [&](int kt) {
        const char* p = asrc + (size_t)kt * (BK * 4);
        av0 = *(const float4*)p;
        av1 = *(const float4*)(p + 16);
    };
    auto stsA = [&](uint32_t stagebase) {
        ns += av0.x * av0.x + av0.y * av0.y + av0.z * av0.z + av0.w * av0.w;
        ns += av1.x * av1.x + av1.y * av1.y + av1.z * av1.z + av1.w * av1.w;
        uint32_t p0 = pack_bf2(av0.x, av0.y);
        uint32_t p1 = pack_bf2(av0.z, av0.w);
        uint32_t p2 = pack_bf2(av1.x, av1.y);
        uint32_t p3 = pack_bf2(av1.z, av1.w);
        asm volatile("st.shared.v4.b32 [%0], {%1,%2,%3,%4};"
                     :: "r"(stagebase + asts), "r"(p0), "r"(p1), "r"(p2), "r"(p3)
                     : "memory");
    };
    auto issueB = [&](int kt) {
        uint32_t stb = sbase + (kt % 3) * STAGE_BYTES;
        CP_ASYNC16(stb + bst0, bsrc0 + (size_t)kt * (BK * 2));
        CP_ASYNC16(stb + bst1, bsrc1 + (size_t)kt * (BK * 2));
    };

    // ---- prologue ----
    issueB(0); CP_COMMIT();
    issueB(1); CP_COMMIT();
    ldgA(0);
    stsA(sbase);             // stage 0
    ldgA(1);

    // ---- mainloop ----
    for (int kt = 0; kt < KITERS; ++kt) {
        CP_WAIT(1);
        __syncthreads();
        if (kt + 2 < KITERS) issueB(kt + 2);
        CP_COMMIT();
        if (kt + 1 < KITERS) stsA(sbase + ((kt + 1) % 3) * STAGE_BYTES);
        if (kt + 2 < KITERS) ldgA(kt + 2);

        const uint32_t stb = sbase + (kt % 3) * STAGE_BYTES;
#pragma unroll
        for (int s = 0; s < 2; ++s) {
            uint32_t af[4][4];
#pragma unroll
            for (int f = 0; f < 4; ++f) {
                uint32_t addr = stb + a_base[f] +
                                (uint32_t)(16 * ((2 * s + ahalf) ^ a_sw[f]));
                asm volatile("ldmatrix.sync.aligned.m8n8.x4.shared.b16 {%0,%1,%2,%3}, [%4];"
                             : "=r"(af[f][0]), "=r"(af[f][1]), "=r"(af[f][2]), "=r"(af[f][3])
                             : "r"(addr));
            }
#pragma unroll
            for (int gp = 0; gp < 2; ++gp) {
                uint32_t bf0, bf1, bf2, bf3;
                uint32_t addr = stb + b_base[gp] +
                                (uint32_t)(16 * ((2 * s + cbit) ^ b_sw[gp]));
                asm volatile("ldmatrix.sync.aligned.m8n8.x4.shared.b16 {%0,%1,%2,%3}, [%4];"
                             : "=r"(bf0), "=r"(bf1), "=r"(bf2), "=r"(bf3)
                             : "r"(addr));
#pragma unroll
                for (int f = 0; f < 4; ++f) {
                    asm volatile(
                        "mma.sync.aligned.m16n8k16.row.col.f32.bf16.bf16.f32 "
                        "{%0,%1,%2,%3}, {%4,%5,%6,%7}, {%8,%9}, {%0,%1,%2,%3};"
                        : "+f"(c[f][2 * gp][0]), "+f"(c[f][2 * gp][1]),
                          "+f"(c[f][2 * gp][2]), "+f"(c[f][2 * gp][3])
                        : "r"(af[f][0]), "r"(af[f][1]), "r"(af[f][2]), "r"(af[f][3]),
                          "r"(bf0), "r"(bf1));
                    asm volatile(
                        "mma.sync.aligned.m16n8k16.row.col.f32.bf16.bf16.f32 "
                        "{%0,%1,%2,%3}, {%4,%5,%6,%7}, {%8,%9}, {%0,%1,%2,%3};"
                        : "+f"(c[f][2 * gp + 1][0]), "+f"(c[f][2 * gp + 1][1]),
                          "+f"(c[f][2 * gp + 1][2]), "+f"(c[f][2 * gp + 1][3])
                        : "r"(af[f][0]), "r"(af[f][1]), "r"(af[f][2]), "r"(af[f][3]),
                          "r"(bf2), "r"(bf3));
                }
            }
        }
    }

    // ---- exact row norms: reduce over the 4 threads sharing a row ----
    {
        float v = ns;
        v += __shfl_xor_sync(0xFFFFFFFFu, v, 1);
        v += __shfl_xor_sync(0xFFFFFFFFu, v, 2);
        if ((tid & 3) == 0) {
            float inv = 1.0f / fmaxf(v, 1e-8f);
            invna_s[arow] = inv;
            if (m0 + arow < U_ROWS) g_inv_na[m0 + arow] = inv;
        }
    }
    __syncthreads();

    // ---- epilogue: scale + direct b-major stores (32B full sectors) ----
#pragma unroll
    for (int f = 0; f < 4; ++f) {
        int r0 = mw * 64 + f * 16 + (lane >> 2);
        float na0 = invna_s[r0];
        float na8 = invna_s[r0 + 8];
        int u0 = m0 + r0;
        bool ok0 = u0 < U_ROWS;
        bool ok8 = (u0 + 8) < U_ROWS;
#pragma unroll
        for (int g = 0; g < 4; ++g) {
            int col = nw * 32 + g * 8 + 2 * (lane & 3);
            float nu0 = invnu_s[col], nu1 = invnu_s[col + 1];
            float* d0 = g_sim + (size_t)col * U_ROWS + u0;
            float* d1 = g_sim + (size_t)(col + 1) * U_ROWS + u0;
            if (ok0) {
                d0[0] = c[f][g][0] * na0 * nu0;
                d1[0] = c[f][g][1] * na0 * nu1;
            }
            if (ok8) {
                d0[8] = c[f][g][2] * na8 * nu0;
                d1[8] = c[f][g][3] * na8 * nu1;
            }
        }
    }
}

// ---------------- kernel 3: approx top-CAND candidate selection -------------
#define LOCK 8
__global__ void topk_cand_kernel() {
    const int b = blockIdx.x;
    const int tid = threadIdx.x;
    const int lane = tid & 31;
    const int wid = tid >> 5;

    float lv[LOCK];
    int   li[LOCK];
#pragma unroll
    for (int j = 0; j < LOCK; j++) { lv[j] = neg_inf(); li[j] = 0x7FFFFFFF; }

    const float* row = g_sim + (size_t)b * U_ROWS;
    for (int u = tid; u < U_ROWS; u += 256) {
        float v = row[u];
        if (v > lv[LOCK - 1]) {
            float cv = v; int ci = u;
#pragma unroll
            for (int j = 0; j < LOCK; j++) {
                if (cv > lv[j]) {
                    float tv = lv[j]; int ti = li[j];
                    lv[j] = cv; li[j] = ci;
                    cv = tv; ci = ti;
                }
            }
        }
    }

    __shared__ unsigned long long wbest[8];
    __shared__ int wtid[8];
    __shared__ int swin;

    for (int r = 0; r < CAND; ++r) {
        unsigned kb = __float_as_uint(lv[0]);
        kb ^= (kb >> 31) ? 0xFFFFFFFFu : 0x80000000u;
        unsigned long long best = ((unsigned long long)kb << 32) |
                                  (unsigned long long)(0xFFFFFFFFu - (unsigned)li[0]);
        int bt = tid;
#pragma unroll
        for (int o = 16; o > 0; o >>= 1) {
            unsigned long long ob = __shfl_down_sync(0xFFFFFFFFu, best, o);
            int ot = __shfl_down_sync(0xFFFFFFFFu, bt, o);
            if (ob > best) { best = ob; bt = ot; }
        }
        if (lane == 0) { wbest[wid] = best; wtid[wid] = bt; }
        __syncthreads();
        if (tid == 0) {
            unsigned long long m = wbest[0]; int mt = wtid[0];
            for (int i = 1; i < 8; i++)
                if (wbest[i] > m) { m = wbest[i]; mt = wtid[i]; }
            swin = mt;
        }
        __syncthreads();
        if (tid == swin) {
            g_cand_idx[b * CAND + r] = li[0];
#pragma unroll
            for (int j = 0; j < LOCK - 1; j++) { lv[j] = lv[j + 1]; li[j] = li[j + 1]; }
            lv[LOCK - 1] = neg_inf(); li[LOCK - 1] = 0x7FFFFFFF;
        }
        __syncthreads();
    }
}

// ---------------- kernel 4: exact fp32 rescore + top-k ----------------------
__global__ void rescore_kernel(const float* __restrict__ F) {
    const int b = blockIdx.x;
    const int tid = threadIdx.x;
    const int lane = tid & 31;
    const int w = tid >> 5;

    __shared__ float ssim[CAND];
    __shared__ int   sidx[CAND];

    const float* ub = g_users + (size_t)b * N_ITEMS;
    for (int cc = w; cc < CAND; cc += 8) {
        int u = g_cand_idx[b * CAND + cc];
        const float* fu = F + (size_t)u * N_ITEMS;
        float acc = 0.f;
        for (int k = lane; k < N_ITEMS; k += 32)
            acc += ub[k] * fu[k];
        for (int o = 16; o > 0; o >>= 1)
            acc += __shfl_down_sync(0xFFFFFFFFu, acc, o);
        if (lane == 0) {
            ssim[cc] = acc * g_inv_na[u] * g_inv_nu[b];
            sidx[cc] = u;
        }
    }
    __syncthreads();

    if (tid == 0) {
        int k = g_k < CAND ? g_k : CAND;
        bool used[CAND];
        for (int i = 0; i < CAND; i++) used[i] = false;
        for (int r = 0; r < k; r++) {
            int bi = -1;
            float bv = neg_inf();
            int bidx = 0x7FFFFFFF;
            for (int cc = 0; cc < CAND; cc++) {
                if (used[cc]) continue;
                float v = ssim[cc];
                if (v > bv || (v == bv && sidx[cc] < bidx)) {
                    bv = v; bidx = sidx[cc]; bi = cc;
                }
            }
            used[bi] = true;
            g_nb_val[b * MAXK + r] = bv;
            g_nb_idx[b * MAXK + r] = bidx;
        }
    }
}

// ---------------- kernel 5: weighted neighbor gather ------------------------
__global__ void ratings_kernel(const float* __restrict__ F, float* __restrict__ out) {
    const int b = blockIdx.x;
    const int tid = threadIdx.x;
    const int k = g_k < CAND ? g_k : CAND;

    __shared__ float w[MAXK];
    __shared__ int   id[MAXK];
    if (tid == 0) {
        float s = 0.f;
        for (int j = 0; j < k; j++) s += g_nb_val[b * MAXK + j];
        float inv = 1.0f / s;
        for (int j = 0; j < k; j++) {
            w[j]  = g_nb_val[b * MAXK + j] * inv;
            id[j] = g_nb_idx[b * MAXK + j];
        }
    }
    __syncthreads();

    for (int i = tid; i < N_ITEMS; i += 256) {
        float acc = 0.f;
        for (int j = 0; j < k; j++)
            acc += w[j] * F[(size_t)id[j] * N_ITEMS + i];
        out[(size_t)b * N_ITEMS + i] = acc;
    }
}

// ---------------- launch ----------------------------------------------------
extern "C" void kernel_launch(void* const* d_in, const int* in_sizes, int n_in,
                              void* d_out, int out_size) {
    const float* F = (const float*)d_in[0];
    const void* ids = d_in[1];
    const int* kptr = (n_in > 2) ? (const int*)d_in[2] : nullptr;

    cudaFuncSetAttribute(gemm_sim_kernel,
                         cudaFuncAttributeMaxDynamicSharedMemorySize, SMEM_TOTAL);

    mode_kernel<<<1, 32>>>(ids, kptr, kptr != nullptr ? 1 : 0);
    gather_users_kernel<<<BATCH, 256>>>(F, ids);

    int grid = (U_ROWS + 127) / 128;   // 391
    gemm_sim_kernel<<<grid, NTHREADS, SMEM_TOTAL>>>(F);

    topk_cand_kernel<<<BATCH, 256>>>();
    rescore_kernel<<<BATCH, 256>>>(F);
    ratings_kernel<<<BATCH, 256>>>(F, (float*)d_out);
}